// round 9
// baseline (speedup 1.0000x reference)
#include <cuda_runtime.h>
#include <cstdint>

// IWT (inverse 2x2 Haar): x (B=16, 4C=256, H=128, W=128) fp32 -> out (B, C=64, 2H, 2W)
//
// h00 = .5(a-b-c+d) -> out[2h,2w]    h01 = .5(a+b-c-d) -> out[2h,2w+1]
// h10 = .5(a-b+c-d) -> out[2h+1,2w]  h11 = .5(a+b+c+d) -> out[2h+1,2w+1]
//
// FINAL (R9 = R7): one-shot per thread: 4x LDG.128 (one per subband) +
// 2x STG.256 (one per output row), factorized butterfly (12 FP ops/lane),
// 28 regs, occ ~78%, launch 16384 x 256.
//
// Session journal (all on sm_103a, ncu-verified):
//   R1 baseline float4/float4         : 74->80us kernel, DRAM 75.8%
//   R2 8-wide threads                 : REGRESSION (44 regs -> occ 48%)
//   R3 .cs hints on v4 path           : neutral
//   R4 STG.128 -> STG.256 fusion      : WIN -10% (DRAM 82.0%, L1 68->41%)
//   R5 persistent single-wave loop    : REGRESSION (serialized per-thread MLP)
//   R6 block 512                      : neutral
//   R7 factorized butterfly           : neutral speed, regs 32->28
//   R8 .cs on v8 store                : neutral
// Plateau: 73.8-74.4us kernel, 82% DRAM, ~6.5 TB/s = HBM ceiling for a
// 1:1 read:write touch-once mix (r/w turnaround bounds below 8 TB/s spec).
// Traffic is minimal (read-once/write-once, all full-sector coalesced);
// no on-chip pipe exceeds 42%. This is the roofline.

#define B_  16
#define C_  64
#define H_  128
#define W_  128
#define SUBBAND_STRIDE_ (C_ * H_ * W_)  // 1,048,576 floats between subband groups
#define OW_ (2 * W_)                    // 256
#define WQ_ (W_ / 4)                    // 32

__device__ __forceinline__ void stg256(float* p,
                                       float v0, float v1, float v2, float v3,
                                       float v4, float v5, float v6, float v7) {
    asm volatile(
        "st.global.v8.f32 [%0], {%1, %2, %3, %4, %5, %6, %7, %8};"
        :: "l"(p), "f"(v0), "f"(v1), "f"(v2), "f"(v3),
           "f"(v4), "f"(v5), "f"(v6), "f"(v7)
        : "memory");
}

__global__ __launch_bounds__(256)
void iwt_kernel(const float* __restrict__ x, float* __restrict__ out) {
    int tid = blockIdx.x * blockDim.x + threadIdx.x;

    int w4   = tid & (WQ_ - 1);          // 0..31
    int rest = tid >> 5;
    int h    = rest & (H_ - 1);          // 0..127
    rest >>= 7;
    int ch   = rest & (C_ - 1);          // 0..63
    int b    = rest >> 6;                // 0..15

    int in_idx = ((b * 256 + ch) * H_ + h) * W_ + (w4 << 2);

    const float4 va = *reinterpret_cast<const float4*>(x + in_idx);
    const float4 vb = *reinterpret_cast<const float4*>(x + in_idx + 1 * SUBBAND_STRIDE_);
    const float4 vc = *reinterpret_cast<const float4*>(x + in_idx + 2 * SUBBAND_STRIDE_);
    const float4 vd = *reinterpret_cast<const float4*>(x + in_idx + 3 * SUBBAND_STRIDE_);

    float h00[4], h01[4], h10[4], h11[4];
    const float av[4] = {va.x, va.y, va.z, va.w};
    const float bv[4] = {vb.x, vb.y, vb.z, vb.w};
    const float cv[4] = {vc.x, vc.y, vc.z, vc.w};
    const float dv[4] = {vd.x, vd.y, vd.z, vd.w};

#pragma unroll
    for (int i = 0; i < 4; i++) {
        float t0 = 0.5f * (av[i] + dv[i]);   // .5(a+d)
        float t1 = 0.5f * (av[i] - dv[i]);   // .5(a-d)
        float t2 = 0.5f * (bv[i] + cv[i]);   // .5(b+c)
        float t3 = 0.5f * (bv[i] - cv[i]);   // .5(b-c)
        h00[i] = t0 - t2;   // .5(a-b-c+d)
        h01[i] = t1 + t3;   // .5(a+b-c-d)
        h10[i] = t1 - t3;   // .5(a-b+c-d)
        h11[i] = t0 + t2;   // .5(a+b+c+d)
    }

    int out_row0 = ((b * C_ + ch) * (2 * H_) + (h << 1)) * OW_ + (w4 << 3);
    int out_row1 = out_row0 + OW_;

    stg256(out + out_row0,
           h00[0], h01[0], h00[1], h01[1], h00[2], h01[2], h00[3], h01[3]);
    stg256(out + out_row1,
           h10[0], h11[0], h10[1], h11[1], h10[2], h11[2], h10[3], h11[3]);
}

extern "C" void kernel_launch(void* const* d_in, const int* in_sizes, int n_in,
                              void* d_out, int out_size) {
    const float* x = (const float*)d_in[0];
    float* out = (float*)d_out;

    const int total_threads = B_ * C_ * H_ * WQ_;  // 4,194,304
    const int block = 256;
    const int grid = total_threads / block;        // 16384

    iwt_kernel<<<grid, block>>>(x, out);
}

// round 10
// speedup vs baseline: 1.0035x; 1.0035x over previous
#include <cuda_runtime.h>
#include <cstdint>

// IWT (inverse 2x2 Haar): x (B=16, 4C=256, H=128, W=128) fp32 -> out (B, C=64, 2H, 2W)
//
// h00 = .5(a-b-c+d) -> out[2h,2w]    h01 = .5(a+b-c-d) -> out[2h,2w+1]
// h10 = .5(a-b+c-d) -> out[2h+1,2w]  h11 = .5(a+b+c+d) -> out[2h+1,2w+1]
//
// FINAL: one-shot per thread: 4x LDG.128 (one per subband) + 2x STG.256
// (one per output row), factorized butterfly (12 FP ops/lane), 28 regs,
// occ ~78-80%, launch 16384 x 256. Best bench: 81.57us (R7).
//
// Session journal (sm_103a, ncu-verified):
//   R1 baseline float4/float4         : DRAM 75.8%
//   R2 8-wide threads                 : REGRESSION (44 regs -> occ 48%)
//   R3 .cs hints on v4 path           : neutral
//   R4 STG.128 -> STG.256 fusion      : WIN -10% (DRAM 82.0%, L1 68->41%)
//   R5 persistent single-wave loop    : REGRESSION (serialized per-thread MLP)
//   R6 block 512                      : neutral
//   R7 factorized butterfly           : neutral speed, regs 32->28 (best bench)
//   R8 .cs on v8 store                : neutral
//   R9 replicate R7                   : plateau reconfirmed
// Four-point plateau: 73.8-74.4us kernel, 82.0+-0.5% DRAM, ~6.5 TB/s.
// Traffic at provable floor; all on-chip pipes <= 42%; TMA path-equivalent
// at LTS cap; channel striding a non-lever on B300. This is the roofline.

#define B_  16
#define C_  64
#define H_  128
#define W_  128
#define SUBBAND_STRIDE_ (C_ * H_ * W_)  // 1,048,576 floats between subband groups
#define OW_ (2 * W_)                    // 256
#define WQ_ (W_ / 4)                    // 32

__device__ __forceinline__ void stg256(float* p,
                                       float v0, float v1, float v2, float v3,
                                       float v4, float v5, float v6, float v7) {
    asm volatile(
        "st.global.v8.f32 [%0], {%1, %2, %3, %4, %5, %6, %7, %8};"
        :: "l"(p), "f"(v0), "f"(v1), "f"(v2), "f"(v3),
           "f"(v4), "f"(v5), "f"(v6), "f"(v7)
        : "memory");
}

__global__ __launch_bounds__(256)
void iwt_kernel(const float* __restrict__ x, float* __restrict__ out) {
    int tid = blockIdx.x * blockDim.x + threadIdx.x;

    int w4   = tid & (WQ_ - 1);          // 0..31
    int rest = tid >> 5;
    int h    = rest & (H_ - 1);          // 0..127
    rest >>= 7;
    int ch   = rest & (C_ - 1);          // 0..63
    int b    = rest >> 6;                // 0..15

    int in_idx = ((b * 256 + ch) * H_ + h) * W_ + (w4 << 2);

    const float4 va = *reinterpret_cast<const float4*>(x + in_idx);
    const float4 vb = *reinterpret_cast<const float4*>(x + in_idx + 1 * SUBBAND_STRIDE_);
    const float4 vc = *reinterpret_cast<const float4*>(x + in_idx + 2 * SUBBAND_STRIDE_);
    const float4 vd = *reinterpret_cast<const float4*>(x + in_idx + 3 * SUBBAND_STRIDE_);

    float h00[4], h01[4], h10[4], h11[4];
    const float av[4] = {va.x, va.y, va.z, va.w};
    const float bv[4] = {vb.x, vb.y, vb.z, vb.w};
    const float cv[4] = {vc.x, vc.y, vc.z, vc.w};
    const float dv[4] = {vd.x, vd.y, vd.z, vd.w};

#pragma unroll
    for (int i = 0; i < 4; i++) {
        float t0 = 0.5f * (av[i] + dv[i]);   // .5(a+d)
        float t1 = 0.5f * (av[i] - dv[i]);   // .5(a-d)
        float t2 = 0.5f * (bv[i] + cv[i]);   // .5(b+c)
        float t3 = 0.5f * (bv[i] - cv[i]);   // .5(b-c)
        h00[i] = t0 - t2;   // .5(a-b-c+d)
        h01[i] = t1 + t3;   // .5(a+b-c-d)
        h10[i] = t1 - t3;   // .5(a-b+c-d)
        h11[i] = t0 + t2;   // .5(a+b+c+d)
    }

    int out_row0 = ((b * C_ + ch) * (2 * H_) + (h << 1)) * OW_ + (w4 << 3);
    int out_row1 = out_row0 + OW_;

    stg256(out + out_row0,
           h00[0], h01[0], h00[1], h01[1], h00[2], h01[2], h00[3], h01[3]);
    stg256(out + out_row1,
           h10[0], h11[0], h10[1], h11[1], h10[2], h11[2], h10[3], h11[3]);
}

extern "C" void kernel_launch(void* const* d_in, const int* in_sizes, int n_in,
                              void* d_out, int out_size) {
    const float* x = (const float*)d_in[0];
    float* out = (float*)d_out;

    const int total_threads = B_ * C_ * H_ * WQ_;  // 4,194,304
    const int block = 256;
    const int grid = total_threads / block;        // 16384

    iwt_kernel<<<grid, block>>>(x, out);
}

// round 11
// speedup vs baseline: 1.0043x; 1.0008x over previous
#include <cuda_runtime.h>
#include <cstdint>

// IWT (inverse 2x2 Haar): x (B=16, 4C=256, H=128, W=128) fp32 -> out (B, C=64, 2H, 2W)
//
// h00 = .5(a-b-c+d) -> out[2h,2w]    h01 = .5(a+b-c-d) -> out[2h,2w+1]
// h10 = .5(a-b+c-d) -> out[2h+1,2w]  h11 = .5(a+b+c+d) -> out[2h+1,2w+1]
//
// FINAL: one-shot per thread: 4x LDG.128 (one per subband) + 2x STG.256
// (one per output row), factorized butterfly (12 FP ops/lane), 28 regs,
// occ ~78%, launch 16384 x 256.
//
// Session journal (sm_103a, ncu-verified):
//   R1 baseline float4/float4         : DRAM 75.8%
//   R2 8-wide threads                 : REGRESSION (44 regs -> occ 48%)
//   R3 .cs hints on v4 path           : neutral
//   R4 STG.128 -> STG.256 fusion      : WIN -10% (DRAM 82.0%, L1 68->41%)
//   R5 persistent single-wave loop    : REGRESSION (serialized per-thread MLP)
//   R6 block 512                      : neutral
//   R7 factorized butterfly           : neutral speed, regs 32->28
//   R8 .cs on v8 store                : neutral
//   R9/R10 replicate                  : plateau confirmed 5x
// Plateau: 73.6-74.4us kernel, 82.2+-0.4% DRAM, ~6.5 TB/s = HBM ceiling
// for a 1:1 read:write touch-once mix. Traffic at provable floor; all
// on-chip pipes <= 42%; TMA path-equivalent at LTS cap; channel striding
// a non-lever on B300; LDG.256-via-shuffle has no mechanism (load-side L1
// at 41%, not binding). This is the roofline.

#define B_  16
#define C_  64
#define H_  128
#define W_  128
#define SUBBAND_STRIDE_ (C_ * H_ * W_)  // 1,048,576 floats between subband groups
#define OW_ (2 * W_)                    // 256
#define WQ_ (W_ / 4)                    // 32

__device__ __forceinline__ void stg256(float* p,
                                       float v0, float v1, float v2, float v3,
                                       float v4, float v5, float v6, float v7) {
    asm volatile(
        "st.global.v8.f32 [%0], {%1, %2, %3, %4, %5, %6, %7, %8};"
        :: "l"(p), "f"(v0), "f"(v1), "f"(v2), "f"(v3),
           "f"(v4), "f"(v5), "f"(v6), "f"(v7)
        : "memory");
}

__global__ __launch_bounds__(256)
void iwt_kernel(const float* __restrict__ x, float* __restrict__ out) {
    int tid = blockIdx.x * blockDim.x + threadIdx.x;

    int w4   = tid & (WQ_ - 1);          // 0..31
    int rest = tid >> 5;
    int h    = rest & (H_ - 1);          // 0..127
    rest >>= 7;
    int ch   = rest & (C_ - 1);          // 0..63
    int b    = rest >> 6;                // 0..15

    int in_idx = ((b * 256 + ch) * H_ + h) * W_ + (w4 << 2);

    const float4 va = *reinterpret_cast<const float4*>(x + in_idx);
    const float4 vb = *reinterpret_cast<const float4*>(x + in_idx + 1 * SUBBAND_STRIDE_);
    const float4 vc = *reinterpret_cast<const float4*>(x + in_idx + 2 * SUBBAND_STRIDE_);
    const float4 vd = *reinterpret_cast<const float4*>(x + in_idx + 3 * SUBBAND_STRIDE_);

    float h00[4], h01[4], h10[4], h11[4];
    const float av[4] = {va.x, va.y, va.z, va.w};
    const float bv[4] = {vb.x, vb.y, vb.z, vb.w};
    const float cv[4] = {vc.x, vc.y, vc.z, vc.w};
    const float dv[4] = {vd.x, vd.y, vd.z, vd.w};

#pragma unroll
    for (int i = 0; i < 4; i++) {
        float t0 = 0.5f * (av[i] + dv[i]);   // .5(a+d)
        float t1 = 0.5f * (av[i] - dv[i]);   // .5(a-d)
        float t2 = 0.5f * (bv[i] + cv[i]);   // .5(b+c)
        float t3 = 0.5f * (bv[i] - cv[i]);   // .5(b-c)
        h00[i] = t0 - t2;   // .5(a-b-c+d)
        h01[i] = t1 + t3;   // .5(a+b-c-d)
        h10[i] = t1 - t3;   // .5(a-b+c-d)
        h11[i] = t0 + t2;   // .5(a+b+c+d)
    }

    int out_row0 = ((b * C_ + ch) * (2 * H_) + (h << 1)) * OW_ + (w4 << 3);
    int out_row1 = out_row0 + OW_;

    stg256(out + out_row0,
           h00[0], h01[0], h00[1], h01[1], h00[2], h01[2], h00[3], h01[3]);
    stg256(out + out_row1,
           h10[0], h11[0], h10[1], h11[1], h10[2], h11[2], h10[3], h11[3]);
}

extern "C" void kernel_launch(void* const* d_in, const int* in_sizes, int n_in,
                              void* d_out, int out_size) {
    const float* x = (const float*)d_in[0];
    float* out = (float*)d_out;

    const int total_threads = B_ * C_ * H_ * WQ_;  // 4,194,304
    const int block = 256;
    const int grid = total_threads / block;        // 16384

    iwt_kernel<<<grid, block>>>(x, out);
}

// round 12
// speedup vs baseline: 1.0047x; 1.0004x over previous
#include <cuda_runtime.h>
#include <cstdint>

// IWT (inverse 2x2 Haar): x (B=16, 4C=256, H=128, W=128) fp32 -> out (B, C=64, 2H, 2W)
//
// h00 = .5(a-b-c+d) -> out[2h,2w]    h01 = .5(a+b-c-d) -> out[2h,2w+1]
// h10 = .5(a-b+c-d) -> out[2h+1,2w]  h11 = .5(a+b+c+d) -> out[2h+1,2w+1]
//
// FINAL (held): one-shot per thread: 4x LDG.128 (one per subband) +
// 2x STG.256 (one per output row), factorized butterfly (12 FP ops/lane),
// 28 regs, occ ~78-80%, launch 16384 x 256.
//
// Session journal (sm_103a, ncu-verified):
//   R1 baseline float4/float4         : DRAM 75.8%
//   R2 8-wide threads                 : REGRESSION (44 regs -> occ 48%)
//   R3 .cs hints on v4 path           : neutral
//   R4 STG.128 -> STG.256 fusion      : WIN -10% (DRAM 82.0%, L1 68->41%)
//   R5 persistent single-wave loop    : REGRESSION (serialized per-thread MLP)
//   R6 block 512                      : neutral
//   R7 factorized butterfly           : neutral speed, regs 32->28
//   R8 .cs on v8 store                : neutral
//   R9-R11 replicate                  : plateau confirmed 6x
// Plateau: 73.6-74.4us kernel, 82.2+-0.4% DRAM, ~6.5 TB/s = HBM ceiling
// for a 1:1 read:write touch-once mix. Traffic at provable floor; all
// on-chip pipes <= 42%. Remaining ideas audited and rejected for lack of
// mechanism: v8 loads (load path not binding + R2 reg cliff), forced reg
// caps (spills add DRAM traffic), TMA (LTS path-independent), striding
// (non-lever on B300). Bench-vs-kernel gap (~8us) is fixed graph-replay
// overhead, invariant across all variants. This is the roofline.

#define B_  16
#define C_  64
#define H_  128
#define W_  128
#define SUBBAND_STRIDE_ (C_ * H_ * W_)  // 1,048,576 floats between subband groups
#define OW_ (2 * W_)                    // 256
#define WQ_ (W_ / 4)                    // 32

__device__ __forceinline__ void stg256(float* p,
                                       float v0, float v1, float v2, float v3,
                                       float v4, float v5, float v6, float v7) {
    asm volatile(
        "st.global.v8.f32 [%0], {%1, %2, %3, %4, %5, %6, %7, %8};"
        :: "l"(p), "f"(v0), "f"(v1), "f"(v2), "f"(v3),
           "f"(v4), "f"(v5), "f"(v6), "f"(v7)
        : "memory");
}

__global__ __launch_bounds__(256)
void iwt_kernel(const float* __restrict__ x, float* __restrict__ out) {
    int tid = blockIdx.x * blockDim.x + threadIdx.x;

    int w4   = tid & (WQ_ - 1);          // 0..31
    int rest = tid >> 5;
    int h    = rest & (H_ - 1);          // 0..127
    rest >>= 7;
    int ch   = rest & (C_ - 1);          // 0..63
    int b    = rest >> 6;                // 0..15

    int in_idx = ((b * 256 + ch) * H_ + h) * W_ + (w4 << 2);

    const float4 va = *reinterpret_cast<const float4*>(x + in_idx);
    const float4 vb = *reinterpret_cast<const float4*>(x + in_idx + 1 * SUBBAND_STRIDE_);
    const float4 vc = *reinterpret_cast<const float4*>(x + in_idx + 2 * SUBBAND_STRIDE_);
    const float4 vd = *reinterpret_cast<const float4*>(x + in_idx + 3 * SUBBAND_STRIDE_);

    float h00[4], h01[4], h10[4], h11[4];
    const float av[4] = {va.x, va.y, va.z, va.w};
    const float bv[4] = {vb.x, vb.y, vb.z, vb.w};
    const float cv[4] = {vc.x, vc.y, vc.z, vc.w};
    const float dv[4] = {vd.x, vd.y, vd.z, vd.w};

#pragma unroll
    for (int i = 0; i < 4; i++) {
        float t0 = 0.5f * (av[i] + dv[i]);   // .5(a+d)
        float t1 = 0.5f * (av[i] - dv[i]);   // .5(a-d)
        float t2 = 0.5f * (bv[i] + cv[i]);   // .5(b+c)
        float t3 = 0.5f * (bv[i] - cv[i]);   // .5(b-c)
        h00[i] = t0 - t2;   // .5(a-b-c+d)
        h01[i] = t1 + t3;   // .5(a+b-c-d)
        h10[i] = t1 - t3;   // .5(a-b+c-d)
        h11[i] = t0 + t2;   // .5(a+b+c+d)
    }

    int out_row0 = ((b * C_ + ch) * (2 * H_) + (h << 1)) * OW_ + (w4 << 3);
    int out_row1 = out_row0 + OW_;

    stg256(out + out_row0,
           h00[0], h01[0], h00[1], h01[1], h00[2], h01[2], h00[3], h01[3]);
    stg256(out + out_row1,
           h10[0], h11[0], h10[1], h11[1], h10[2], h11[2], h10[3], h11[3]);
}

extern "C" void kernel_launch(void* const* d_in, const int* in_sizes, int n_in,
                              void* d_out, int out_size) {
    const float* x = (const float*)d_in[0];
    float* out = (float*)d_out;

    const int total_threads = B_ * C_ * H_ * WQ_;  // 4,194,304
    const int block = 256;
    const int grid = total_threads / block;        // 16384

    iwt_kernel<<<grid, block>>>(x, out);
}

// round 13
// speedup vs baseline: 1.0051x; 1.0004x over previous
#include <cuda_runtime.h>
#include <cstdint>

// IWT (inverse 2x2 Haar): x (B=16, 4C=256, H=128, W=128) fp32 -> out (B, C=64, 2H, 2W)
//
// h00 = .5(a-b-c+d) -> out[2h,2w]    h01 = .5(a+b-c-d) -> out[2h,2w+1]
// h10 = .5(a-b+c-d) -> out[2h+1,2w]  h11 = .5(a+b+c+d) -> out[2h+1,2w+1]
//
// FINAL (held, 7x reproduced): one-shot per thread: 4x LDG.128 (one per
// subband) + 2x STG.256 (one per output row), factorized butterfly
// (12 FP ops/lane), 28 regs, occ ~78-80%, launch 16384 x 256.
//
// Session journal (sm_103a, ncu-verified):
//   R1 baseline float4/float4         : DRAM 75.8%
//   R2 8-wide threads                 : REGRESSION (44 regs -> occ 48%)
//   R3 .cs hints on v4 path           : neutral
//   R4 STG.128 -> STG.256 fusion      : WIN -10% (DRAM 82.0%, L1 68->41%)
//   R5 persistent single-wave loop    : REGRESSION (serialized per-thread MLP)
//   R6 block 512                      : neutral
//   R7 factorized butterfly           : neutral speed, regs 32->28
//   R8 .cs on v8 store                : neutral
//   R9-R12 replicate                  : plateau confirmed 7x
// Plateau: 73.6-74.4us kernel (sigma 0.25us), 82.2+-0.4% DRAM, ~6.5 TB/s
// = HBM ceiling for a 1:1 read:write touch-once mix. Traffic at provable
// floor (read-once/write-once, full-sector coalesced); all on-chip pipes
// <= 42%. Residual vs 8 TB/s spec is DRAM r/w turnaround + refresh -- a
// controller property, not SM-addressable. Remaining ideas rejected for
// lack of mechanism: v8 loads (load path idle + reg cliff), reg caps
// (spills add traffic), TMA (LTS path-independent), striding (B300
// non-lever). Bench-vs-kernel gap (~8us) is fixed graph-replay overhead.

#define B_  16
#define C_  64
#define H_  128
#define W_  128
#define SUBBAND_STRIDE_ (C_ * H_ * W_)  // 1,048,576 floats between subband groups
#define OW_ (2 * W_)                    // 256
#define WQ_ (W_ / 4)                    // 32

__device__ __forceinline__ void stg256(float* p,
                                       float v0, float v1, float v2, float v3,
                                       float v4, float v5, float v6, float v7) {
    asm volatile(
        "st.global.v8.f32 [%0], {%1, %2, %3, %4, %5, %6, %7, %8};"
        :: "l"(p), "f"(v0), "f"(v1), "f"(v2), "f"(v3),
           "f"(v4), "f"(v5), "f"(v6), "f"(v7)
        : "memory");
}

__global__ __launch_bounds__(256)
void iwt_kernel(const float* __restrict__ x, float* __restrict__ out) {
    int tid = blockIdx.x * blockDim.x + threadIdx.x;

    int w4   = tid & (WQ_ - 1);          // 0..31
    int rest = tid >> 5;
    int h    = rest & (H_ - 1);          // 0..127
    rest >>= 7;
    int ch   = rest & (C_ - 1);          // 0..63
    int b    = rest >> 6;                // 0..15

    int in_idx = ((b * 256 + ch) * H_ + h) * W_ + (w4 << 2);

    const float4 va = *reinterpret_cast<const float4*>(x + in_idx);
    const float4 vb = *reinterpret_cast<const float4*>(x + in_idx + 1 * SUBBAND_STRIDE_);
    const float4 vc = *reinterpret_cast<const float4*>(x + in_idx + 2 * SUBBAND_STRIDE_);
    const float4 vd = *reinterpret_cast<const float4*>(x + in_idx + 3 * SUBBAND_STRIDE_);

    float h00[4], h01[4], h10[4], h11[4];
    const float av[4] = {va.x, va.y, va.z, va.w};
    const float bv[4] = {vb.x, vb.y, vb.z, vb.w};
    const float cv[4] = {vc.x, vc.y, vc.z, vc.w};
    const float dv[4] = {vd.x, vd.y, vd.z, vd.w};

#pragma unroll
    for (int i = 0; i < 4; i++) {
        float t0 = 0.5f * (av[i] + dv[i]);   // .5(a+d)
        float t1 = 0.5f * (av[i] - dv[i]);   // .5(a-d)
        float t2 = 0.5f * (bv[i] + cv[i]);   // .5(b+c)
        float t3 = 0.5f * (bv[i] - cv[i]);   // .5(b-c)
        h00[i] = t0 - t2;   // .5(a-b-c+d)
        h01[i] = t1 + t3;   // .5(a+b-c-d)
        h10[i] = t1 - t3;   // .5(a-b+c-d)
        h11[i] = t0 + t2;   // .5(a+b+c+d)
    }

    int out_row0 = ((b * C_ + ch) * (2 * H_) + (h << 1)) * OW_ + (w4 << 3);
    int out_row1 = out_row0 + OW_;

    stg256(out + out_row0,
           h00[0], h01[0], h00[1], h01[1], h00[2], h01[2], h00[3], h01[3]);
    stg256(out + out_row1,
           h10[0], h11[0], h10[1], h11[1], h10[2], h11[2], h10[3], h11[3]);
}

extern "C" void kernel_launch(void* const* d_in, const int* in_sizes, int n_in,
                              void* d_out, int out_size) {
    const float* x = (const float*)d_in[0];
    float* out = (float*)d_out;

    const int total_threads = B_ * C_ * H_ * WQ_;  // 4,194,304
    const int block = 256;
    const int grid = total_threads / block;        // 16384

    iwt_kernel<<<grid, block>>>(x, out);
}